// round 9
// baseline (speedup 1.0000x reference)
#include <cuda_runtime.h>
#include <stdint.h>

// Problem sizes (fixed by the dataset: B=16, T=2048, D=512, K=1024)
#define N_TOK 32768
#define DIM   512
#define KCB   1024

#define DECAY 0.99f
#define OMD   0.01f
#define EPS_C 1e-5f

// ---------------- scratch (no allocations allowed) ----------------
// __device__ symbols referenced ONLY from device code (host passes raw ptrs).
__device__ float g_c2[KCB];
__device__ float g_z2[N_TOK];
__device__ int   g_idx[N_TOK];
__device__ float g_counts[KCB];
__device__ float g_sums[KCB * DIM];
__device__ float g_newcs[KCB];
__device__ float g_ntot;
__device__ float g_norm[KCB * DIM];

// ---------------- zero accumulators ----------------
__global__ void zero_kernel() {
    int t = blockIdx.x * blockDim.x + threadIdx.x;
    int stride = gridDim.x * blockDim.x;
    for (int i = t; i < KCB * DIM; i += stride) g_sums[i] = 0.0f;
    if (t < KCB) g_counts[t] = 0.0f;
}

// ---------------- row sum-of-squares ----------------
__device__ __forceinline__ float row_sumsq(const float* __restrict__ src, int r, int t) {
    const float4* row = (const float4*)(src + (size_t)r * DIM);
    float4 v = row[t];
    float s = v.x * v.x + v.y * v.y + v.z * v.z + v.w * v.w;
    #pragma unroll
    for (int o = 16; o > 0; o >>= 1) s += __shfl_down_sync(0xffffffffu, s, o);
    __shared__ float ws[4];
    if ((t & 31) == 0) ws[t >> 5] = s;
    __syncthreads();
    return ws[0] + ws[1] + ws[2] + ws[3];
}

__global__ void c2_kernel(const float* __restrict__ cb) {
    float s = row_sumsq(cb, blockIdx.x, threadIdx.x);   // 128 threads
    if (threadIdx.x == 0) g_c2[blockIdx.x] = s;
}

__global__ void z2_kernel(const float* __restrict__ z) {
    float s = row_sumsq(z, blockIdx.x, threadIdx.x);    // 128 threads
    if (threadIdx.x == 0) g_z2[blockIdx.x] = s;
}

// ---------------- distance GEMM + argmin ----------------
// EXACT EMULATION of the reference's fp32 arithmetic:
//   d2(n,k) = fl( fl(z2_n - 2*dot) + c2_k ),
// dot = sequential ascending-d fp32 FMA chain per code (cublas/Eigen order).
// Argmin keeps the LOWEST index among fp32-equal scores.
//
// 128 rows x 128-code chunks, BD=16 depth slabs, 256 threads, 8x8 per-thread
// micro-tile, f32x2 packed FMA (lanes = 2 adjacent codes). A compact in smem
// ({a,a} pairs built in regs). Double-buffered stages, 1 barrier per stage.
// __launch_bounds__(256,2): reg cap 128 -> 2 CTAs/SM (R6 sat at 129 regs =
// exactly one over the 2-CTA boundary; occupancy was the binder).
#define BM 128
#define BN 128
#define BD 16
#define PA 132   // compact A pitch (128 data + 4 pad, 16B-divisible)
#define PB 132   // B pitch (128 data + 4 pad, 16B-divisible)
#define NSTAGE 256  // (KCB/BN) * (DIM/BD)

// dynamic smem: 2 A-stages + 2 B-stages + c2all + z2s   (38400 bytes)
#define SM_A_FLOATS (2 * BD * PA)
#define SM_B_FLOATS (2 * BD * PB)
#define SM_TOTAL_BYTES ((SM_A_FLOATS + SM_B_FLOATS + KCB + BM) * 4)

#define FMA2(d, a, b) \
    asm("fma.rn.f32x2 %0, %1, %2, %0;" : "+l"(d) : "l"(a), "l"(b))
#define PACK2(d, v) \
    asm("mov.b64 %0, {%1, %1};" : "=l"(d) : "f"(v))

// Pack (score, index) into u64 so unsigned min == (min value, then min index).
__device__ __forceinline__ unsigned long long packkey(float s, int k) {
    unsigned b = __float_as_uint(s);
    b = (b & 0x80000000u) ? ~b : (b | 0x80000000u);
    return ((unsigned long long)b << 32) | (unsigned)k;
}

__global__ __launch_bounds__(256, 2)
void dist_kernel(const float* __restrict__ z, const float* __restrict__ cb) {
    extern __shared__ __align__(16) unsigned char sraw[];
    float* AsBuf = (float*)sraw;                                   // [2][BD][PA] compact
    float* BsBuf = (float*)(sraw + SM_A_FLOATS * 4);               // [2][BD][PB]
    float* c2all = (float*)(sraw + (SM_A_FLOATS + SM_B_FLOATS) * 4);
    float* z2s   = c2all + KCB;
    unsigned long long* red = (unsigned long long*)sraw;           // 16KB overlay (post-loop)

    const int tid = threadIdx.x;
    const int tx  = tid & 15;   // col group (8 codes)
    const int ty  = tid >> 4;   // row group (8 rows)
    const int rb  = blockIdx.x * BM;

    // persistent smem: all 1024 c2 + this block's 128 z2
    #pragma unroll
    for (int i = 0; i < KCB / 256; i++) c2all[tid + i * 256] = g_c2[tid + i * 256];
    if (tid < BM) z2s[tid] = g_z2[rb + tid];

    float minv[8];
    int   mina[8];
    #pragma unroll
    for (int i = 0; i < 8; i++) { minv[i] = 3.4e38f; mina[i] = 0; }

    // global-load lane mapping: 512 float4 per stage, 2 per thread
    const int lr = tid >> 2;   // 0..63 (row), second load at lr+64
    const int lf = tid & 3;    // which float4 within the 16-float depth slab
    const float* zA  = z  + (size_t)(rb + lr) * DIM + lf * 4;
    const float* cbB = cb + (size_t)lr * DIM + lf * 4;

    unsigned long long acc[8][4];
    #pragma unroll
    for (int i = 0; i < 8; i++)
        #pragma unroll
        for (int j = 0; j < 4; j++) acc[i][j] = 0ull;

    float4 a0, a1, b0, b1;

    #define LDG_STAGE(s) do {                                              \
        int dt_ = (s) & 31, ch_ = (s) >> 5;                                \
        const float* pA_ = zA + dt_ * BD;                                  \
        a0 = *(const float4*)pA_;                                          \
        a1 = *(const float4*)(pA_ + 64 * DIM);                             \
        const float* pB_ = cbB + (size_t)ch_ * (BN * DIM) + dt_ * BD;      \
        b0 = *(const float4*)pB_;                                          \
        b1 = *(const float4*)(pB_ + 64 * DIM);                             \
    } while (0)

    // compact A staging: As[d][row] = z[row][d]
    #define STS_STAGE(p) do {                                              \
        float* Ad_ = AsBuf + (p) * (BD * PA);                              \
        float* Bd_ = BsBuf + (p) * (BD * PB);                              \
        int dbase_ = lf * 4;                                               \
        _Pragma("unroll")                                                  \
        for (int c_ = 0; c_ < 4; c_++) {                                   \
            Ad_[(dbase_ + c_) * PA + lr]      = (&a0.x)[c_];               \
            Ad_[(dbase_ + c_) * PA + lr + 64] = (&a1.x)[c_];               \
            Bd_[(dbase_ + c_) * PB + lr]      = (&b0.x)[c_];               \
            Bd_[(dbase_ + c_) * PB + lr + 64] = (&b1.x)[c_];               \
        }                                                                  \
    } while (0)

    // prologue: fill buffer 0 with stage 0, hold stage 1 in regs
    LDG_STAGE(0);
    STS_STAGE(0);
    LDG_STAGE(1);
    __syncthreads();

    #pragma unroll 1
    for (int s = 0; s < NSTAGE; s++) {
        const int p = s & 1;
        // regs hold stage s+1: store into the other buffer (its readers from
        // stage s-1 finished at the last barrier), then prefetch stage s+2.
        if (s < NSTAGE - 1) STS_STAGE(p ^ 1);
        if (s < NSTAGE - 2) LDG_STAGE(s + 2);

        const float* Ap = AsBuf + p * (BD * PA);
        const float* Bp = BsBuf + p * (BD * PB);
        #pragma unroll
        for (int dd = 0; dd < BD; dd++) {
            // A: 8 rows, compact, tx-broadcast (2 x LDS.128)
            float4 f0 = *(const float4*)&Ap[dd * PA + ty * 8];
            float4 f1 = *(const float4*)&Ap[dd * PA + ty * 8 + 4];
            // B: 8 codes (2 x LDS.128)
            ulonglong2 bA = *(const ulonglong2*)&Bp[dd * PB + tx * 8];
            ulonglong2 bB = *(const ulonglong2*)&Bp[dd * PB + tx * 8 + 4];
            unsigned long long ar[8];
            PACK2(ar[0], f0.x); PACK2(ar[1], f0.y);
            PACK2(ar[2], f0.z); PACK2(ar[3], f0.w);
            PACK2(ar[4], f1.x); PACK2(ar[5], f1.y);
            PACK2(ar[6], f1.z); PACK2(ar[7], f1.w);
            unsigned long long br[4] = {bA.x, bA.y, bB.x, bB.y};
            #pragma unroll
            for (int i = 0; i < 8; i++)
                #pragma unroll
                for (int j = 0; j < 4; j++)
                    FMA2(acc[i][j], ar[i], br[j]);
        }

        // chunk epilogue: reference-exact scoring + running argmin
        if ((s & 31) == 31) {
            const int ch = (s >> 5) * BN;
            #pragma unroll
            for (int i = 0; i < 8; i++) {
                float z2v = z2s[ty * 8 + i];
                #pragma unroll
                for (int j = 0; j < 4; j++) {
                    unsigned long long pck = acc[i][j];
                    float dlo = __uint_as_float((unsigned)(pck & 0xffffffffull));
                    float dhi = __uint_as_float((unsigned)(pck >> 32));
                    int c0 = tx * 8 + 2 * j;
                    // fl(z2 - 2*dot) via single fma (2*dot exact), then
                    // un-fused add of c2 — bit-identical to the reference.
                    float t0 = fmaf(-2.0f, dlo, z2v);
                    float t1 = fmaf(-2.0f, dhi, z2v);
                    float s0 = __fadd_rn(t0, c2all[ch + c0]);
                    float s1 = __fadd_rn(t1, c2all[ch + c0 + 1]);
                    if (s0 < minv[i]) { minv[i] = s0; mina[i] = ch + c0; }
                    if (s1 < minv[i]) { minv[i] = s1; mina[i] = ch + c0 + 1; }
                    acc[i][j] = 0ull;
                }
            }
        }
        __syncthreads();
    }

    // cross-thread argmin reduce via packed keys (u64 min == value, then index)
    #pragma unroll
    for (int i = 0; i < 8; i++) {
        int r = ty * 8 + i;
        red[r * 16 + tx] = packkey(minv[i], mina[i]);
    }
    __syncthreads();
    if (tid < BM) {
        unsigned long long m1 = ~0ull;
        #pragma unroll
        for (int x = 0; x < 16; x++) {
            unsigned long long v = red[tid * 16 + x];
            if (v < m1) m1 = v;
        }
        g_idx[rb + tid] = (int)(m1 & 0xffffffffull);
    }
    #undef LDG_STAGE
    #undef STS_STAGE
}

// ---------------- scatter: counts[k] += 1, sums[k] += z_n ----------------
__global__ void scatter_kernel(const float* __restrict__ z) {
    int g = blockIdx.x * blockDim.x + threadIdx.x;
    int row = g >> 5;
    int lane = g & 31;
    if (row >= N_TOK) return;
    int k = g_idx[row];
    const float4* zr = (const float4*)(z + (size_t)row * DIM);
    float* dst = g_sums + (size_t)k * DIM;
    #pragma unroll
    for (int i = 0; i < 4; i++) {
        int e = lane + i * 32;
        float4 v = zr[e];
        atomicAdd(dst + 4 * e + 0, v.x);
        atomicAdd(dst + 4 * e + 1, v.y);
        atomicAdd(dst + 4 * e + 2, v.z);
        atomicAdd(dst + 4 * e + 3, v.w);
    }
    if (lane == 0) atomicAdd(&g_counts[k], 1.0f);
}

// ---------------- EMA cluster sizes + total n ----------------
__global__ void newcs_kernel(const float* __restrict__ ema_cs) {
    __shared__ float red[1024];
    int t = threadIdx.x;  // 1024 threads
    float v = DECAY * ema_cs[t] + OMD * g_counts[t];
    g_newcs[t] = v;
    red[t] = v;
    __syncthreads();
    for (int s = 512; s > 0; s >>= 1) {
        if (t < s) red[t] += red[t + s];
        __syncthreads();
    }
    if (t == 0) g_ntot = red[0];
}

// ---------------- normalized codebook ----------------
__global__ void norm_kernel(const float* __restrict__ ema_w) {
    int k = blockIdx.x;
    int t = threadIdx.x;  // 128 threads
    float n = g_ntot;
    float cs = g_newcs[k];
    float smoothed = (cs + EPS_C) / (n + (float)KCB * EPS_C) * n;
    float inv = 1.0f / smoothed;
    const float4* w = (const float4*)(ema_w + (size_t)k * DIM);
    const float4* s = (const float4*)(g_sums + (size_t)k * DIM);
    float4* o = (float4*)(g_norm + (size_t)k * DIM);
    float4 wv = w[t], sv = s[t], ov;
    ov.x = (DECAY * wv.x + OMD * sv.x) * inv;
    ov.y = (DECAY * wv.y + OMD * sv.y) * inv;
    ov.z = (DECAY * wv.z + OMD * sv.z) * inv;
    ov.w = (DECAY * wv.w + OMD * sv.w) * inv;
    o[t] = ov;
}

// ---------------- gather + emit outputs ----------------
__global__ void out_kernel(const float* __restrict__ z,
                           float* __restrict__ idx_out,
                           float* __restrict__ q_out,
                           float* __restrict__ st_out) {
    int row = blockIdx.x;
    int t = threadIdx.x;  // 128 threads
    int k = g_idx[row];
    const float4* nr = (const float4*)(g_norm + (size_t)k * DIM);
    float4 qv = nr[t];
    if (q_out)
        ((float4*)(q_out + (size_t)row * DIM))[t] = qv;
    if (st_out) {
        const float4* zr = (const float4*)(z + (size_t)row * DIM);
        float4 zv = zr[t];
        float4 sv;
        sv.x = zv.x + (qv.x - zv.x);  // mirror reference fp ops exactly
        sv.y = zv.y + (qv.y - zv.y);
        sv.z = zv.z + (qv.z - zv.z);
        sv.w = zv.w + (qv.w - zv.w);
        ((float4*)(st_out + (size_t)row * DIM))[t] = sv;
    }
    if (idx_out && t == 0) idx_out[row] = (float)k;
}

// ---------------- host launcher ----------------
extern "C" void kernel_launch(void* const* d_in, const int* in_sizes, int n_in,
                              void* d_out, int out_size) {
    const float* z   = (const float*)d_in[0];  // [B*T, D]
    const float* cb  = (const float*)d_in[1];  // [K, D]
    const float* ecs = (const float*)d_in[2];  // [K]
    const float* ew  = (const float*)d_in[3];  // [K, D]
    float* out = (float*)d_out;

    zero_kernel<<<512, 256>>>();
    c2_kernel<<<KCB, 128>>>(cb);
    z2_kernel<<<N_TOK, 128>>>(z);
    dist_kernel<<<N_TOK / BM, 256, SM_TOTAL_BYTES>>>(z, cb);
    scatter_kernel<<<(N_TOK * 32) / 256, 256>>>(z);
    newcs_kernel<<<1, 1024>>>(ecs);
    norm_kernel<<<KCB, 128>>>(ew);

    // Output layout: reference returns (idx, quantized, quantized_st),
    // flattened+concatenated into one float32 buffer. Dispatch on out_size.
    const long long N = N_TOK, D = DIM;
    const long long os = out_size;
    float *idxp = nullptr, *qp = nullptr, *stp = nullptr;
    if (os == N * (2 * D + 1)) {            // [idx, q, q_st]
        idxp = out; qp = out + N; stp = out + N + N * D;
    } else if (os == N * 2 * D) {           // [q, q_st]
        qp = out; stp = out + N * D;
    } else if (os == N * D) {               // single [q] (q == q_st)
        qp = out;
    } else if (os == N) {                   // [idx]
        idxp = out;
    } else {                                // fallback: fill everything we can
        idxp = out;
        if (os >= N + N * D) qp = out + N;
        if (os >= N + 2 * N * D) stp = out + N + N * D;
    }
    out_kernel<<<N_TOK, 128>>>(z, idxp, qp, stp);
}

// round 11
// speedup vs baseline: 1.1980x; 1.1980x over previous
#include <cuda_runtime.h>
#include <cuda_bf16.h>
#include <mma.h>
#include <stdint.h>

using namespace nvcuda;

#define N_TOK 32768
#define DIM   512
#define KCB   1024

#define DECAY 0.99f
#define OMD   0.01f
#define EPS_C 1e-5f
#define MARGIN 0.15f   // ~40 sigma of bf16 score error

// ---------------- scratch (no allocations allowed) ----------------
__device__ float g_c2[KCB];
__device__ float g_z2[N_TOK];
__device__ int   g_idx[N_TOK];
__device__ float g_counts[KCB];
__device__ float g_sums[KCB * DIM];
__device__ float g_newcs[KCB];
__device__ float g_ntot;
__device__ float g_norm[KCB * DIM];
__device__ __align__(16) __nv_bfloat16 g_zh[N_TOK * (size_t)DIM];
__device__ __align__(16) __nv_bfloat16 g_cbh[KCB * DIM];
__device__ float g_scores[(size_t)KCB * N_TOK];   // [code][row]

// ---------------- zero accumulators ----------------
__global__ void zero_kernel() {
    int t = blockIdx.x * blockDim.x + threadIdx.x;
    int stride = gridDim.x * blockDim.x;
    for (int i = t; i < KCB * DIM; i += stride) g_sums[i] = 0.0f;
    if (t < KCB) g_counts[t] = 0.0f;
}

// ---------------- c2/z2 + fused bf16 conversion ----------------
__global__ void c2_kernel(const float* __restrict__ cb) {
    int k = blockIdx.x, t = threadIdx.x;  // 128 threads
    float4 v = ((const float4*)(cb + (size_t)k * DIM))[t];
    union { __nv_bfloat162 h[2]; uint2 u; } cv;
    cv.h[0] = __floats2bfloat162_rn(v.x, v.y);
    cv.h[1] = __floats2bfloat162_rn(v.z, v.w);
    ((uint2*)(g_cbh + (size_t)k * DIM))[t] = cv.u;
    float s = v.x * v.x + v.y * v.y + v.z * v.z + v.w * v.w;
    #pragma unroll
    for (int o = 16; o > 0; o >>= 1) s += __shfl_down_sync(0xffffffffu, s, o);
    __shared__ float ws[4];
    if ((t & 31) == 0) ws[t >> 5] = s;
    __syncthreads();
    if (t == 0) g_c2[k] = ws[0] + ws[1] + ws[2] + ws[3];
}

__global__ void z2_kernel(const float* __restrict__ z) {
    int r = blockIdx.x, t = threadIdx.x;  // 128 threads
    float4 v = ((const float4*)(z + (size_t)r * DIM))[t];
    union { __nv_bfloat162 h[2]; uint2 u; } cv;
    cv.h[0] = __floats2bfloat162_rn(v.x, v.y);
    cv.h[1] = __floats2bfloat162_rn(v.z, v.w);
    ((uint2*)(g_zh + (size_t)r * DIM))[t] = cv.u;
    float s = v.x * v.x + v.y * v.y + v.z * v.z + v.w * v.w;
    #pragma unroll
    for (int o = 16; o > 0; o >>= 1) s += __shfl_down_sync(0xffffffffu, s, o);
    __shared__ float ws[4];
    if ((t & 31) == 0) ws[t >> 5] = s;
    __syncthreads();
    if (t == 0) g_z2[r] = ws[0] + ws[1] + ws[2] + ws[3];
}

// ---------------- HMMA (wmma bf16) candidate GEMM ----------------
// Per CTA: 128 rows x 8 chunks of 128 codes; K=512 in 8 slabs of 64.
// Warp (8 total): 32 rows x 64 codes = 2x4 fragments of 16x16.
// Epilogue: acc stored col-major into smem [code][row], then coalesced
// write of approx score = c2 - 2*dot into g_scores[code][row].
#define PAW 72     // A/B smem pitch in bf16 (64 data + 8 pad)
#define PCW 132    // C smem pitch in f32 (128 rows + 4 pad)
#define OFF_A 0
#define OFF_B 18432
#define OFF_C 36864
#define OFF_C2 104448
#define GSM_SIZE 104960

__global__ __launch_bounds__(256)
void gemm_kernel() {
    extern __shared__ __align__(16) unsigned char sm[];
    __nv_bfloat16* As = (__nv_bfloat16*)(sm + OFF_A);   // [128][PAW]
    __nv_bfloat16* Bs = (__nv_bfloat16*)(sm + OFF_B);   // [128][PAW]
    float* Cs  = (float*)(sm + OFF_C);                  // [128 codes][PCW]
    float* c2s = (float*)(sm + OFF_C2);                 // [128]

    const int tid = threadIdx.x;
    const int wid = tid >> 5;
    const int wr = wid & 3;    // row group: rows wr*32
    const int wc = wid >> 2;   // col group: codes wc*64
    const int rb = blockIdx.x * 128;

    wmma::fragment<wmma::matrix_a, 16, 16, 16, __nv_bfloat16, wmma::row_major> af[2];
    wmma::fragment<wmma::matrix_b, 16, 16, 16, __nv_bfloat16, wmma::col_major> bf[4];
    wmma::fragment<wmma::accumulator, 16, 16, 16, float> acc[2][4];

    for (int ch = 0; ch < 8; ch++) {
        if (tid < 128) c2s[tid] = g_c2[ch * 128 + tid];
        #pragma unroll
        for (int f = 0; f < 2; f++)
            #pragma unroll
            for (int g = 0; g < 4; g++)
                wmma::fill_fragment(acc[f][g], 0.0f);

        for (int slab = 0; slab < 8; slab++) {
            // stage A[128][64] and B[128][64] bf16 (uint4 = 8 bf16)
            #pragma unroll
            for (int i = 0; i < 4; i++) {
                int idx = i * 256 + tid;           // 0..1023
                int r = idx >> 3, grp = idx & 7;
                *(uint4*)(As + r * PAW + grp * 8) =
                    *(const uint4*)(g_zh + (size_t)(rb + r) * DIM + slab * 64 + grp * 8);
            }
            #pragma unroll
            for (int i = 0; i < 4; i++) {
                int idx = i * 256 + tid;
                int n = idx >> 3, grp = idx & 7;
                *(uint4*)(Bs + n * PAW + grp * 8) =
                    *(const uint4*)(g_cbh + (size_t)(ch * 128 + n) * DIM + slab * 64 + grp * 8);
            }
            __syncthreads();

            #pragma unroll
            for (int ks = 0; ks < 4; ks++) {
                #pragma unroll
                for (int f = 0; f < 2; f++)
                    wmma::load_matrix_sync(af[f],
                        As + (wr * 32 + f * 16) * PAW + ks * 16, PAW);
                #pragma unroll
                for (int g = 0; g < 4; g++)
                    wmma::load_matrix_sync(bf[g],
                        Bs + (wc * 64 + g * 16) * PAW + ks * 16, PAW);
                #pragma unroll
                for (int f = 0; f < 2; f++)
                    #pragma unroll
                    for (int g = 0; g < 4; g++)
                        wmma::mma_sync(acc[f][g], af[f], bf[g], acc[f][g]);
            }
            __syncthreads();
        }

        // store acc col-major: element (row r, code c) -> Cs[c*PCW + r]
        #pragma unroll
        for (int f = 0; f < 2; f++)
            #pragma unroll
            for (int g = 0; g < 4; g++)
                wmma::store_matrix_sync(
                    Cs + (wc * 64 + g * 16) * PCW + wr * 32 + f * 16,
                    acc[f][g], PCW, wmma::mem_col_major);
        __syncthreads();

        // coalesced transposed write: score = c2 - 2*dot
        #pragma unroll
        for (int i = 0; i < 64; i++) {
            int idx = i * 256 + tid;
            int r = idx & 127;
            int c = idx >> 7;
            float dot = Cs[c * PCW + r];
            g_scores[(size_t)(ch * 128 + c) * N_TOK + rb + r] =
                fmaf(-2.0f, dot, c2s[c]);
        }
        __syncthreads();
    }
}

// ---------------- scan + EXACT fp32 rerank ----------------
// Pass 1: approx min per row. Pass 2: candidates within MARGIN.
// Each candidate re-scored with the exact reference arithmetic
// (sequential ascending-d fp32 chain, fl(fl(z2-2dot)+c2), lowest-index
// tie-break) — identical formula to the R4/R7 passing kernels.
__global__ __launch_bounds__(128)
void scan_rerank_kernel(const float* __restrict__ z, const float* __restrict__ cb) {
    int row = blockIdx.x * 128 + threadIdx.x;
    float mn = 3.4e38f;
    for (int c = 0; c < KCB; c++)
        mn = fminf(mn, g_scores[(size_t)c * N_TOK + row]);
    float thr = mn + MARGIN;
    int cand[16];
    int nc = 0;
    for (int c = 0; c < KCB; c++) {
        if (g_scores[(size_t)c * N_TOK + row] <= thr) {
            if (nc < 16) cand[nc] = c;
            nc++;
        }
    }
    float z2v = g_z2[row];
    const float* zr = z + (size_t)row * DIM;
    float best = 3.4e38f;
    int bi = 0;
    if (nc <= 16) {
        for (int i = 0; i < nc; i++) {
            int code = cand[i];
            const float* cr = cb + (size_t)code * DIM;
            float dot = 0.0f;
            #pragma unroll 8
            for (int d = 0; d < DIM; d++) dot = fmaf(zr[d], cr[d], dot);
            float t = fmaf(-2.0f, dot, z2v);
            float sc = __fadd_rn(t, g_c2[code]);
            if (sc < best) { best = sc; bi = code; }
        }
    } else {  // overflow fallback: exact scan of all codes (prob ~0)
        for (int code = 0; code < KCB; code++) {
            const float* cr = cb + (size_t)code * DIM;
            float dot = 0.0f;
            #pragma unroll 8
            for (int d = 0; d < DIM; d++) dot = fmaf(zr[d], cr[d], dot);
            float t = fmaf(-2.0f, dot, z2v);
            float sc = __fadd_rn(t, g_c2[code]);
            if (sc < best) { best = sc; bi = code; }
        }
    }
    g_idx[row] = bi;
}

// ---------------- scatter: counts[k] += 1, sums[k] += z_n ----------------
__global__ void scatter_kernel(const float* __restrict__ z) {
    int g = blockIdx.x * blockDim.x + threadIdx.x;
    int row = g >> 5;
    int lane = g & 31;
    if (row >= N_TOK) return;
    int k = g_idx[row];
    const float4* zr = (const float4*)(z + (size_t)row * DIM);
    float* dst = g_sums + (size_t)k * DIM;
    #pragma unroll
    for (int i = 0; i < 4; i++) {
        int e = lane + i * 32;
        float4 v = zr[e];
        atomicAdd(dst + 4 * e + 0, v.x);
        atomicAdd(dst + 4 * e + 1, v.y);
        atomicAdd(dst + 4 * e + 2, v.z);
        atomicAdd(dst + 4 * e + 3, v.w);
    }
    if (lane == 0) atomicAdd(&g_counts[k], 1.0f);
}

// ---------------- EMA cluster sizes + total n ----------------
__global__ void newcs_kernel(const float* __restrict__ ema_cs) {
    __shared__ float red[1024];
    int t = threadIdx.x;  // 1024 threads
    float v = DECAY * ema_cs[t] + OMD * g_counts[t];
    g_newcs[t] = v;
    red[t] = v;
    __syncthreads();
    for (int s = 512; s > 0; s >>= 1) {
        if (t < s) red[t] += red[t + s];
        __syncthreads();
    }
    if (t == 0) g_ntot = red[0];
}

// ---------------- normalized codebook ----------------
__global__ void norm_kernel(const float* __restrict__ ema_w) {
    int k = blockIdx.x;
    int t = threadIdx.x;  // 128 threads
    float n = g_ntot;
    float cs = g_newcs[k];
    float smoothed = (cs + EPS_C) / (n + (float)KCB * EPS_C) * n;
    float inv = 1.0f / smoothed;
    const float4* w = (const float4*)(ema_w + (size_t)k * DIM);
    const float4* s = (const float4*)(g_sums + (size_t)k * DIM);
    float4* o = (float4*)(g_norm + (size_t)k * DIM);
    float4 wv = w[t], sv = s[t], ov;
    ov.x = (DECAY * wv.x + OMD * sv.x) * inv;
    ov.y = (DECAY * wv.y + OMD * sv.y) * inv;
    ov.z = (DECAY * wv.z + OMD * sv.z) * inv;
    ov.w = (DECAY * wv.w + OMD * sv.w) * inv;
    o[t] = ov;
}

// ---------------- gather + emit outputs ----------------
__global__ void out_kernel(const float* __restrict__ z,
                           float* __restrict__ idx_out,
                           float* __restrict__ q_out,
                           float* __restrict__ st_out) {
    int row = blockIdx.x;
    int t = threadIdx.x;  // 128 threads
    int k = g_idx[row];
    const float4* nr = (const float4*)(g_norm + (size_t)k * DIM);
    float4 qv = nr[t];
    if (q_out)
        ((float4*)(q_out + (size_t)row * DIM))[t] = qv;
    if (st_out) {
        const float4* zr = (const float4*)(z + (size_t)row * DIM);
        float4 zv = zr[t];
        float4 sv;
        sv.x = zv.x + (qv.x - zv.x);
        sv.y = zv.y + (qv.y - zv.y);
        sv.z = zv.z + (qv.z - zv.z);
        sv.w = zv.w + (qv.w - zv.w);
        ((float4*)(st_out + (size_t)row * DIM))[t] = sv;
    }
    if (idx_out && t == 0) idx_out[row] = (float)k;
}

// ---------------- host launcher ----------------
extern "C" void kernel_launch(void* const* d_in, const int* in_sizes, int n_in,
                              void* d_out, int out_size) {
    const float* z   = (const float*)d_in[0];
    const float* cb  = (const float*)d_in[1];
    const float* ecs = (const float*)d_in[2];
    const float* ew  = (const float*)d_in[3];
    float* out = (float*)d_out;

    static bool attr_set = false;
    if (!attr_set) {
        cudaFuncSetAttribute(gemm_kernel,
                             cudaFuncAttributeMaxDynamicSharedMemorySize,
                             GSM_SIZE);
        attr_set = true;
    }

    zero_kernel<<<512, 256>>>();
    c2_kernel<<<KCB, 128>>>(cb);
    z2_kernel<<<N_TOK, 128>>>(z);
    gemm_kernel<<<N_TOK / 128, 256, GSM_SIZE>>>();
    scan_rerank_kernel<<<N_TOK / 128, 128>>>(z, cb);
    scatter_kernel<<<(N_TOK * 32) / 256, 256>>>(z);
    newcs_kernel<<<1, 1024>>>(ecs);
    norm_kernel<<<KCB, 128>>>(ew);

    const long long N = N_TOK, D = DIM;
    const long long os = out_size;
    float *idxp = nullptr, *qp = nullptr, *stp = nullptr;
    if (os == N * (2 * D + 1)) {            // [idx, q, q_st]
        idxp = out; qp = out + N; stp = out + N + N * D;
    } else if (os == N * 2 * D) {           // [q, q_st]
        qp = out; stp = out + N * D;
    } else if (os == N * D) {               // [q]
        qp = out;
    } else if (os == N) {                   // [idx]
        idxp = out;
    } else {
        idxp = out;
        if (os >= N + N * D) qp = out + N;
        if (os >= N + 2 * N * D) stp = out + N + N * D;
    }
    out_kernel<<<N_TOK, 128>>>(z, idxp, qp, stp);
}